// round 10
// baseline (speedup 1.0000x reference)
#include <cuda_runtime.h>

// FoRefLoss: sum over B rows of (dx^2 + dy^2 + wrapped_angle^2), B=8388608.
// Champion codegen + naturally-static masks: grid = 1152 CTAs x 256 threads,
// stride = 294912 ≡ 0 (mod 3), so each thread's mod-3 residue (hence its
// angle-component mask) is loop-invariant — no per-iteration m update, no
// per-iteration ISETPs — while the loop body/schedule is otherwise identical
// to the reproduced champion (simple body, `#pragma unroll 2`, no manual
// batching). Single wave (1152 <= 1184 = 8 CTAs/SM cap).
// Angle term in turn-space: t = 2*min(frac(|d|), 1-frac(|d|)), term t^2.
// Single kernel; last-arriving block reduces partials in fixed order
// (deterministic across replays).

#define NBLOCKS 1152
#define NTHREADS 256

__device__ float g_partials[NBLOCKS];
__device__ unsigned int g_arrived = 0;

__device__ __forceinline__ float vcomp(float p, float l, bool is_angle) {
    float d = p - l;              // difference in "turns" (full circle = 1.0)
    float ad = fabsf(d);
    float f = ad - floorf(ad);    // frac in [0,1)
    float w = fminf(f, 1.0f - f); // folded to [0, 0.5]
    return is_angle ? (w + w) : d; // angle: 2w = clamped_angle/pi; else diff
}

__global__ void __launch_bounds__(NTHREADS)
foref_loss_kernel(const float4* __restrict__ pred,
                  const float4* __restrict__ lab,
                  int n4,                 // total float4 count per tensor
                  float* __restrict__ out)
{
    const int stride = NBLOCKS * NTHREADS;      // 294912; 294912 % 3 == 0
    int tid0 = blockIdx.x * NTHREADS + threadIdx.x;

    float sum = 0.0f;
    int iters = n4 / stride;   // 21 for n4 = 6291456 (tail = 98304 float4s)

    // stride ≡ 0 (mod 3): residue is loop-invariant -> static masks.
    int m = tid0 % 3;
    const bool aA = (m == 2);   // components 0 and 3 of the float4
    const bool aB = (m == 1);   // component 1
    const bool aC = (m == 0);   // component 2

    int k = tid0;

    #pragma unroll 2
    for (int it = 0; it < iters; ++it) {
        float4 p = pred[k];
        float4 l = lab[k];
        float v;
        v = vcomp(p.x, l.x, aA); sum = fmaf(v, v, sum);
        v = vcomp(p.y, l.y, aB); sum = fmaf(v, v, sum);
        v = vcomp(p.z, l.z, aC); sum = fmaf(v, v, sum);
        v = vcomp(p.w, l.w, aA); sum = fmaf(v, v, sum);
        k += stride;
    }
    // tail: leftover < stride, at most one extra float4 per thread; masks
    // unchanged because stride ≡ 0 (mod 3).
    if (k < n4) {
        float4 p = pred[k];
        float4 l = lab[k];
        float v;
        v = vcomp(p.x, l.x, aA); sum = fmaf(v, v, sum);
        v = vcomp(p.y, l.y, aB); sum = fmaf(v, v, sum);
        v = vcomp(p.z, l.z, aC); sum = fmaf(v, v, sum);
        v = vcomp(p.w, l.w, aA); sum = fmaf(v, v, sum);
    }

    // intra-block reduce
    #pragma unroll
    for (int off = 16; off > 0; off >>= 1)
        sum += __shfl_down_sync(0xFFFFFFFFu, sum, off);

    __shared__ float smem[NTHREADS / 32];
    __shared__ bool is_last;
    int lane = threadIdx.x & 31;
    int wid  = threadIdx.x >> 5;
    if (lane == 0) smem[wid] = sum;
    __syncthreads();

    if (wid == 0) {
        float v = (lane < NTHREADS / 32) ? smem[lane] : 0.0f;
        #pragma unroll
        for (int off = 4; off > 0; off >>= 1)
            v += __shfl_down_sync(0xFFFFFFFFu, v, off);
        if (lane == 0) {
            g_partials[blockIdx.x] = v;
            __threadfence();
            unsigned int t = atomicAdd(&g_arrived, 1u);
            is_last = (t == (unsigned int)(gridDim.x - 1));
        }
    }
    __syncthreads();

    if (is_last) {
        // all partials are globally visible now; reduce in fixed order
        float v = 0.0f;
        for (int i = threadIdx.x; i < NBLOCKS; i += NTHREADS)
            v += g_partials[i];

        #pragma unroll
        for (int off = 16; off > 0; off >>= 1)
            v += __shfl_down_sync(0xFFFFFFFFu, v, off);

        if (lane == 0) smem[wid] = v;
        __syncthreads();

        if (wid == 0) {
            float t2 = (lane < NTHREADS / 32) ? smem[lane] : 0.0f;
            #pragma unroll
            for (int off = 4; off > 0; off >>= 1)
                t2 += __shfl_down_sync(0xFFFFFFFFu, t2, off);
            if (lane == 0) {
                out[0] = t2;
                g_arrived = 0;  // reset for next graph replay
            }
        }
    }
}

extern "C" void kernel_launch(void* const* d_in, const int* in_sizes, int n_in,
                              void* d_out, int out_size)
{
    const float4* pred = (const float4*)d_in[0];
    const float4* lab  = (const float4*)d_in[1];
    float* out = (float*)d_out;

    int n_floats = in_sizes[0];   // 25165824
    int n4 = n_floats / 4;        // 6291456

    foref_loss_kernel<<<NBLOCKS, NTHREADS>>>(pred, lab, n4, out);
}